// round 4
// baseline (speedup 1.0000x reference)
#include <cuda_runtime.h>
#include <math.h>

#define HID 2048
#define SEQ 2048
#define NHEADS 16
#define HDIM 128
#define GROUPS_PER_W (HID*HID/128)   // 32768

// ---------------- scratch (static device memory; no allocation) ----------------
__device__ float g_w[4][(size_t)HID*HID];            // dequantized wq,wk,wv,wo  (67 MB)
__device__ float g_y[3][(size_t)SEQ*HID];            // q,k,v projections        (50 MB)
__device__ float g_scores[(size_t)NHEADS*SEQ*SEQ];   // per-head scores/probs    (256 MB)
__device__ float g_attn[(size_t)SEQ*HID];            // attention output         (17 MB)

// ---------------- ternary group-wise quantize + dequantize ----------------
__device__ __forceinline__ float quant1(float w, float scale) {
    float wn = w / scale;
    float q = wn > 0.5f ? 1.f : (wn < -0.5f ? -1.f : 0.f);
    return q * scale;
}

__global__ void quantize_kernel(const float* __restrict__ w0, const float* __restrict__ w1,
                                const float* __restrict__ w2, const float* __restrict__ w3) {
    const float* srcs[4] = {w0, w1, w2, w3};
    const float* w = srcs[blockIdx.y];
    float* out = g_w[blockIdx.y];
    int warp = threadIdx.x >> 5, lane = threadIdx.x & 31;
    size_t g = (size_t)blockIdx.x * 8 + warp;        // group index (groups are contiguous)
    const float* src = w + g * 128 + lane * 4;
    float4 v = *(const float4*)src;
    float s = fabsf(v.x) + fabsf(v.y) + fabsf(v.z) + fabsf(v.w);
    #pragma unroll
    for (int o = 16; o; o >>= 1) s += __shfl_xor_sync(0xffffffffu, s, o);
    float scale = fmaxf(s * (1.f / 128.f), 1e-8f);
    float4 r;
    r.x = quant1(v.x, scale); r.y = quant1(v.y, scale);
    r.z = quant1(v.z, scale); r.w = quant1(v.w, scale);
    *(float4*)(out + g * 128 + lane * 4) = r;
}

// ---------------- generic fp32 GEMM: C[M,N] = A[M,K] @ op(B) ----------------
// BT=true:  B is [N,K] row-major (C = A B^T).  BT=false: B is [K,N] row-major.
// CAUSAL_SKIP: skip output blocks entirely above the diagonal (scores).
// CAUSAL_K:    limit K loop to (by+1)*BM (PV with zero probs beyond diagonal).
#define BM 128
#define BN 128
#define BKK 8

template<bool BT, bool CAUSAL_SKIP, bool CAUSAL_K>
__global__ void __launch_bounds__(256)
gemm_f32(const float* __restrict__ A, const float* __restrict__ B, float* __restrict__ C,
         int M, int N, int K, int lda, int ldb, int ldc,
         long long sA, long long sB, long long sC)
{
    int bx = blockIdx.x, by = blockIdx.y, bz = blockIdx.z;
    if (CAUSAL_SKIP && bx * BN > by * BM + (BM - 1)) return;
    A += (long long)bz * sA;
    B += (long long)bz * sB;
    C += (long long)bz * sC;

    __shared__ __align__(16) float As[BKK][BM];
    __shared__ __align__(16) float Bs[BKK][BN];

    int tid = threadIdx.x;
    int arow = tid >> 1;             // 0..127
    int acol = (tid & 1) << 2;       // 0 or 4
    int nn_row = tid >> 5;           // 0..7   (NN B load)
    int nn_col = (tid & 31) << 2;    // 0..124

    int Keff = K;
    if (CAUSAL_K) { int lim = (by + 1) * BM; if (lim < Keff) Keff = lim; }

    const float* Aptr = A + (long long)(by * BM + arow) * lda + acol;
    const float* Bptr;
    if (BT) Bptr = B + (long long)(bx * BN + arow) * ldb + acol;
    else    Bptr = B + (long long)nn_row * ldb + bx * BN + nn_col;

    float acc[8][8];
    #pragma unroll
    for (int i = 0; i < 8; i++)
        #pragma unroll
        for (int j = 0; j < 8; j++) acc[i][j] = 0.f;

    int tx = tid & 15, ty = tid >> 4;

    for (int k0 = 0; k0 < Keff; k0 += BKK) {
        float4 av = *(const float4*)(Aptr + k0);
        As[acol + 0][arow] = av.x; As[acol + 1][arow] = av.y;
        As[acol + 2][arow] = av.z; As[acol + 3][arow] = av.w;
        if (BT) {
            float4 bv = *(const float4*)(Bptr + k0);
            Bs[acol + 0][arow] = bv.x; Bs[acol + 1][arow] = bv.y;
            Bs[acol + 2][arow] = bv.z; Bs[acol + 3][arow] = bv.w;
        } else {
            float4 bv = *(const float4*)(Bptr + (long long)k0 * ldb);
            *(float4*)&Bs[nn_row][nn_col] = bv;
        }
        __syncthreads();
        #pragma unroll
        for (int k = 0; k < BKK; k++) {
            float4 a0 = *(const float4*)&As[k][ty * 4];
            float4 a1 = *(const float4*)&As[k][64 + ty * 4];
            float4 b0 = *(const float4*)&Bs[k][tx * 4];
            float4 b1 = *(const float4*)&Bs[k][64 + tx * 4];
            float ar[8] = {a0.x, a0.y, a0.z, a0.w, a1.x, a1.y, a1.z, a1.w};
            float br[8] = {b0.x, b0.y, b0.z, b0.w, b1.x, b1.y, b1.z, b1.w};
            #pragma unroll
            for (int i = 0; i < 8; i++)
                #pragma unroll
                for (int j = 0; j < 8; j++) acc[i][j] += ar[i] * br[j];
        }
        __syncthreads();
    }

    #pragma unroll
    for (int ih = 0; ih < 2; ih++)
        #pragma unroll
        for (int i = 0; i < 4; i++) {
            int m = by * BM + ih * 64 + ty * 4 + i;
            float* crow = C + (long long)m * ldc + bx * BN;
            float4 v0 = make_float4(acc[ih*4+i][0], acc[ih*4+i][1], acc[ih*4+i][2], acc[ih*4+i][3]);
            float4 v1 = make_float4(acc[ih*4+i][4], acc[ih*4+i][5], acc[ih*4+i][6], acc[ih*4+i][7]);
            *(float4*)(crow + tx * 4)      = v0;
            *(float4*)(crow + 64 + tx * 4) = v1;
        }
}

// ---------------- RoPE (in place on y[s, h*128+d]) ----------------
__global__ void rope_kernel(float* __restrict__ yq, float* __restrict__ yk) {
    int idx = blockIdx.x * blockDim.x + threadIdx.x;     // s*1024 + h*64 + j
    float* y = (blockIdx.y == 0) ? yq : yk;
    int j = idx & 63;
    int h = (idx >> 6) & 15;
    int s = idx >> 10;
    float inv = (float)(1.0 / pow(10000.0, (double)j / 64.0));
    float f = (float)s * inv;                             // fp32-rounded angle (matches ref)
    double fd = (double)f;
    float c  = (float)cos(fd);
    float sn = (float)sin(fd);
    float* p = y + (size_t)s * HID + h * HDIM + j;
    float x1 = p[0], x2 = p[64];
    p[0]  = x1 * c  - x2 * sn;
    p[64] = x1 * sn + x2 * c;
}

// ---------------- row softmax (causal + pad mask, zero-fill t>s) ----------------
__device__ __forceinline__ float blockReduce(float v, bool isMax) {
    __shared__ float sh[8];
    #pragma unroll
    for (int o = 16; o; o >>= 1) {
        float t = __shfl_xor_sync(0xffffffffu, v, o);
        v = isMax ? fmaxf(v, t) : (v + t);
    }
    int w = threadIdx.x >> 5, l = threadIdx.x & 31;
    if (l == 0) sh[w] = v;
    __syncthreads();
    if (w == 0) {
        float t = (l < 8) ? sh[l] : (isMax ? -INFINITY : 0.f);
        #pragma unroll
        for (int o = 4; o; o >>= 1) {
            float u = __shfl_xor_sync(0xffffffffu, t, o);
            t = isMax ? fmaxf(t, u) : (t + u);
        }
        if (l == 0) sh[0] = t;
    }
    __syncthreads();
    float r = sh[0];
    __syncthreads();
    return r;
}

__global__ void softmax_kernel(float* __restrict__ scores, const int* __restrict__ mask) {
    int s = blockIdx.x, h = blockIdx.y;
    float* row = scores + ((long long)h * SEQ + s) * SEQ;
    int valid = s + 1;
    const float scale = 0.088388347648318447f;   // 1/sqrt(128)
    float mx = -INFINITY;
    for (int t = threadIdx.x; t < valid; t += blockDim.x)
        if (mask[t] != 0) mx = fmaxf(mx, row[t] * scale);
    mx = blockReduce(mx, true);
    float sum = 0.f;
    for (int t = threadIdx.x; t < valid; t += blockDim.x) {
        float e = (mask[t] != 0) ? expf(row[t] * scale - mx) : 0.f;
        row[t] = e;
        sum += e;
    }
    sum = blockReduce(sum, false);
    float invsum = 1.f / sum;
    for (int t = threadIdx.x; t < valid; t += blockDim.x) row[t] *= invsum;
    for (int t = valid + threadIdx.x; t < SEQ; t += blockDim.x) row[t] = 0.f;
}

// ---------------- launch ----------------
extern "C" void kernel_launch(void* const* d_in, const int* in_sizes, int n_in,
                              void* d_out, int out_size) {
    const float* x    = (const float*)d_in[0];
    const int*   mask = (const int*)d_in[1];
    const float* wq   = (const float*)d_in[2];
    const float* wk   = (const float*)d_in[3];
    const float* wv   = (const float*)d_in[4];
    const float* wo   = (const float*)d_in[5];

    float *pw, *py, *ps, *pa;
    cudaGetSymbolAddress((void**)&pw, g_w);
    cudaGetSymbolAddress((void**)&py, g_y);
    cudaGetSymbolAddress((void**)&ps, g_scores);
    cudaGetSymbolAddress((void**)&pa, g_attn);
    const size_t WSZ = (size_t)HID * HID;
    float* wdq = pw;            float* wdk = pw + WSZ;
    float* wdv = pw + 2 * WSZ;  float* wdo = pw + 3 * WSZ;
    float* yq = py;             float* yk = py + WSZ;
    float* yv = py + 2 * WSZ;

    // 1. quantize all four weights
    quantize_kernel<<<dim3(GROUPS_PER_W / 8, 4), 256>>>(wq, wk, wv, wo);

    // 2. Q/K/V projections  (C = X @ W^T)
    dim3 g16(HID / BN, SEQ / BM, 1);
    gemm_f32<true,  false, false><<<g16, 256>>>(x, wdq, yq, SEQ, HID, HID, HID, HID, HID, 0, 0, 0);
    gemm_f32<true,  false, false><<<g16, 256>>>(x, wdk, yk, SEQ, HID, HID, HID, HID, HID, 0, 0, 0);
    gemm_f32<true,  false, false><<<g16, 256>>>(x, wdv, yv, SEQ, HID, HID, HID, HID, HID, 0, 0, 0);

    // 3. RoPE on Q and K (in place)
    rope_kernel<<<dim3(SEQ * NHEADS * 64 / 256, 2), 256>>>(yq, yk);

    // 4. scores = Q K^T per head (batched over grid.z, causal block skip)
    gemm_f32<true,  true,  false><<<dim3(SEQ / BN, SEQ / BM, NHEADS), 256>>>(
        yq, yk, ps, SEQ, SEQ, HDIM, HID, HID, SEQ,
        /*sA=*/HDIM, /*sB=*/HDIM, /*sC=*/(long long)SEQ * SEQ);

    // 5. softmax rows (scale + causal + pad mask, zero-fill)
    softmax_kernel<<<dim3(SEQ, NHEADS), 256>>>(ps, mask);

    // 6. attn = P @ V per head (NN GEMM, causal K-limit), writes [s, h*128+d]
    gemm_f32<false, false, true ><<<dim3(HDIM / BN, SEQ / BM, NHEADS), 256>>>(
        ps, yv, pa, SEQ, HDIM, SEQ, SEQ, HID, HID,
        /*sA=*/(long long)SEQ * SEQ, /*sB=*/HDIM, /*sC=*/HDIM);

    // 7. out = attn @ Wo^T  -> d_out
    gemm_f32<true,  false, false><<<g16, 256>>>(pa, wdo, (float*)d_out,
                                                SEQ, HID, HID, HID, HID, HID, 0, 0, 0);
}

// round 9
// speedup vs baseline: 1.5145x; 1.5145x over previous
#include <cuda_runtime.h>
#include <cuda_bf16.h>
#include <stdint.h>
#include <math.h>

#define HID 2048
#define SEQ 2048
#define NHEADS 16
#define HDIM 128
#define GROUPS_PER_W (HID*HID/128)

typedef __nv_bfloat16 bf16;

// ---------------- scratch (static device memory; no allocation) ----------------
__device__ __align__(256) bf16  g_xhi[(size_t)SEQ*HID],  g_xlo[(size_t)SEQ*HID];
__device__ __align__(256) bf16  g_whi[4][(size_t)HID*HID], g_wlo[4][(size_t)HID*HID];
__device__ __align__(256) float g_qf[(size_t)SEQ*HID],  g_kf[(size_t)SEQ*HID];
__device__ __align__(256) bf16  g_qhi[(size_t)SEQ*HID], g_qlo[(size_t)SEQ*HID];
__device__ __align__(256) bf16  g_khi[(size_t)SEQ*HID], g_klo[(size_t)SEQ*HID];
__device__ __align__(256) bf16  g_vthi[(size_t)SEQ*HID], g_vtlo[(size_t)SEQ*HID]; // V^T per head [o][t]
__device__ __align__(256) float g_s[(size_t)NHEADS*SEQ*SEQ];                       // scores fp32
__device__ __align__(256) bf16  g_phi[(size_t)NHEADS*SEQ*SEQ], g_plo[(size_t)NHEADS*SEQ*SEQ];
__device__ __align__(256) bf16  g_ahi[(size_t)SEQ*HID], g_alo[(size_t)SEQ*HID];

// ---------------- small helpers ----------------
__device__ __forceinline__ void split(float v, bf16& h, bf16& l) {
    h = __float2bfloat16(v);
    l = __float2bfloat16(v - __bfloat162float(h));
}
__device__ __forceinline__ uint32_t pack2(bf16 a, bf16 b) {
    uint16_t ua = *(uint16_t*)&a, ub = *(uint16_t*)&b;
    return (uint32_t)ua | ((uint32_t)ub << 16);
}
__device__ __forceinline__ uint32_t smem_u32(const void* p) {
    uint32_t a;
    asm("{ .reg .u64 t; cvta.to.shared.u64 t, %1; cvt.u32.u64 %0, t; }" : "=r"(a) : "l"(p));
    return a;
}

// ---------------- warp-mma primitives (baseline PTX, sm_80+) ----------------
__device__ __forceinline__ void ldsm4(uint32_t& r0, uint32_t& r1, uint32_t& r2, uint32_t& r3,
                                      uint32_t addr) {
    asm volatile("ldmatrix.sync.aligned.m8n8.x4.shared.b16 {%0,%1,%2,%3}, [%4];"
                 : "=r"(r0), "=r"(r1), "=r"(r2), "=r"(r3) : "r"(addr));
}
__device__ __forceinline__ void mma16816(float* c, const uint32_t* a, const uint32_t* b) {
    asm volatile(
        "mma.sync.aligned.m16n8k16.row.col.f32.bf16.bf16.f32 "
        "{%0,%1,%2,%3}, {%4,%5,%6,%7}, {%8,%9}, {%0,%1,%2,%3};"
        : "+f"(c[0]), "+f"(c[1]), "+f"(c[2]), "+f"(c[3])
        : "r"(a[0]), "r"(a[1]), "r"(a[2]), "r"(a[3]), "r"(b[0]), "r"(b[1]));
}

// ---------------- quantize: w -> ternary*scale -> bf16 hi/lo ----------------
__global__ void quantize_kernel(const float* __restrict__ w0, const float* __restrict__ w1,
                                const float* __restrict__ w2, const float* __restrict__ w3) {
    const float* srcs[4] = {w0, w1, w2, w3};
    const float* w = srcs[blockIdx.y];
    bf16* ohi = g_whi[blockIdx.y];
    bf16* olo = g_wlo[blockIdx.y];
    int warp = threadIdx.x >> 5, lane = threadIdx.x & 31;
    size_t g = (size_t)blockIdx.x * 8 + warp;
    float4 v = *(const float4*)(w + g * 128 + lane * 4);
    float s = fabsf(v.x) + fabsf(v.y) + fabsf(v.z) + fabsf(v.w);
    #pragma unroll
    for (int o = 16; o; o >>= 1) s += __shfl_xor_sync(0xffffffffu, s, o);
    float scale = fmaxf(s * (1.f / 128.f), 1e-8f);
    float q[4];
    float wn;
    wn = v.x / scale; q[0] = (wn > 0.5f ? scale : (wn < -0.5f ? -scale : 0.f));
    wn = v.y / scale; q[1] = (wn > 0.5f ? scale : (wn < -0.5f ? -scale : 0.f));
    wn = v.z / scale; q[2] = (wn > 0.5f ? scale : (wn < -0.5f ? -scale : 0.f));
    wn = v.w / scale; q[3] = (wn > 0.5f ? scale : (wn < -0.5f ? -scale : 0.f));
    bf16 h[4], l[4];
    #pragma unroll
    for (int i = 0; i < 4; i++) split(q[i], h[i], l[i]);
    *(uint2*)(ohi + g * 128 + lane * 4) = make_uint2(pack2(h[0], h[1]), pack2(h[2], h[3]));
    *(uint2*)(olo + g * 128 + lane * 4) = make_uint2(pack2(l[0], l[1]), pack2(l[2], l[3]));
}

// ---------------- fp32 -> bf16 hi/lo converter (for x) ----------------
__global__ void convert_kernel(const float* __restrict__ src, bf16* __restrict__ hi,
                               bf16* __restrict__ lo) {
    int i = blockIdx.x * 256 + threadIdx.x;
    float4 v = ((const float4*)src)[i];
    bf16 h0,l0,h1,l1,h2,l2,h3,l3;
    split(v.x,h0,l0); split(v.y,h1,l1); split(v.z,h2,l2); split(v.w,h3,l3);
    ((uint2*)hi)[i] = make_uint2(pack2(h0,h1), pack2(h2,h3));
    ((uint2*)lo)[i] = make_uint2(pack2(l0,l1), pack2(l2,l3));
}

// ---------------- RoPE: fp32 q/k -> roped bf16 hi/lo ----------------
__global__ void rope_kernel(const float* __restrict__ qf, const float* __restrict__ kf,
                            bf16* __restrict__ qhi, bf16* __restrict__ qlo,
                            bf16* __restrict__ khi, bf16* __restrict__ klo) {
    int idx = blockIdx.x * blockDim.x + threadIdx.x;
    const float* y = (blockIdx.y == 0) ? qf : kf;
    bf16* oh = (blockIdx.y == 0) ? qhi : khi;
    bf16* ol = (blockIdx.y == 0) ? qlo : klo;
    int j = idx & 63;
    int h = (idx >> 6) & 15;
    int s = idx >> 10;
    float inv = (float)(1.0 / pow(10000.0, (double)j / 64.0));
    float f = (float)s * inv;
    double fd = (double)f;
    float c  = (float)cos(fd);
    float sn = (float)sin(fd);
    size_t p = (size_t)s * HID + h * HDIM + j;
    float x1 = y[p], x2 = y[p + 64];
    float o1 = x1 * c - x2 * sn;
    float o2 = x1 * sn + x2 * c;
    bf16 hh, ll;
    split(o1, hh, ll); oh[p] = hh;      ol[p] = ll;
    split(o2, hh, ll); oh[p + 64] = hh; ol[p + 64] = ll;
}

// ---------------- warp-mma GEMM: C[M,N] = (Ahi+Alo)(Bhi+Blo)^T ----------------
// Both operands K-major row-major [rows, K]. 128x128 CTA tile, K-chunk 32.
// OUT: 0 = fp32 C, 1 = bf16 hi/lo split C, 2 = bf16 hi/lo split TRANSPOSED C.
#define KC 32
#define ROWB 80                  // padded bytes per smem row (conflict-free ldmatrix)
#define TILEB (128*ROWB)         // 10240 B per operand tile
#define BUFB  (4*TILEB)          // 40960 B per stage (Ahi,Alo,Bhi,Blo)
#define SMEM_SZ (2*BUFB)         // 81920 B double-buffered

template<int OUT, bool CSKIP, bool CK>
__global__ void __launch_bounds__(256, 1)
gemm_mma(const bf16* __restrict__ Ahi, const bf16* __restrict__ Alo,
         const bf16* __restrict__ Bhi, const bf16* __restrict__ Blo,
         float* __restrict__ Cf, bf16* __restrict__ Chi, bf16* __restrict__ Clo,
         int K, int lda, int ldb, int ldc,
         long long sA, long long sB, long long sC)
{
    int bx = blockIdx.x, by = blockIdx.y, bz = blockIdx.z;
    if (CSKIP && bx > by) return;
    Ahi += (long long)bz * sA;  Alo += (long long)bz * sA;
    Bhi += (long long)bz * sB;  Blo += (long long)bz * sB;
    Cf  += (long long)bz * sC;  Chi += (long long)bz * sC;  Clo += (long long)bz * sC;

    extern __shared__ char smem[];
    uint32_t sb = smem_u32(smem);

    int tid = threadIdx.x;
    int lane = tid & 31, wid = tid >> 5;
    int wm = wid & 1;            // 2 M groups of 64
    int wn = wid >> 1;           // 4 N groups of 32

    int Keff = K;
    if (CK) { int lim = (by + 1) * 128; if (lim < Keff) Keff = lim; }
    int NC = Keff >> 5;

    const bf16* const srcs[4] = {Ahi, Alo, Bhi, Blo};
    const int ldsv[4] = {lda, lda, ldb, ldb};
    const int r0v[4]  = {by*128, by*128, bx*128, bx*128};
    int row0 = tid >> 2, seg = tid & 3;

    uint4 stg[8];
    auto ldg = [&](int c) {
        int k0 = c * KC;
        #pragma unroll
        for (int tl = 0; tl < 4; tl++) {
            const bf16* s = srcs[tl]; int ld = ldsv[tl]; int r0 = r0v[tl];
            stg[tl*2+0] = *(const uint4*)(s + (long long)(r0 + row0)      * ld + k0 + seg*8);
            stg[tl*2+1] = *(const uint4*)(s + (long long)(r0 + row0 + 64) * ld + k0 + seg*8);
        }
    };
    auto sts = [&](int buf) {
        char* bp = smem + buf * BUFB;
        #pragma unroll
        for (int tl = 0; tl < 4; tl++) {
            *(uint4*)(bp + tl*TILEB + row0*ROWB + seg*16)        = stg[tl*2+0];
            *(uint4*)(bp + tl*TILEB + (row0+64)*ROWB + seg*16)   = stg[tl*2+1];
        }
    };

    float acc[4][4][4];
    #pragma unroll
    for (int i = 0; i < 4; i++)
        #pragma unroll
        for (int j = 0; j < 4; j++)
            #pragma unroll
            for (int r = 0; r < 4; r++) acc[i][j][r] = 0.f;

    ldg(0); sts(0); __syncthreads();

    uint32_t arow = wm*64 + (lane & 7) + ((lane >> 3) & 1) * 8;   // + mt*16
    uint32_t brow = wn*32 + (lane & 7) + ((lane >> 3) & 1) * 8;   // + np*16
    uint32_t kcol = ((lane >> 4) & 1) * 16;                       // k8 half offset (bytes)

    for (int c = 0; c < NC; c++) {
        int cb = c & 1, nb = (c + 1) & 1;
        bool pf = (c + 1 < NC);
        if (pf) ldg(c + 1);

        uint32_t base = sb + cb * BUFB;
        #pragma unroll
        for (int ks = 0; ks < 2; ks++) {
            uint32_t af[2][4][4];
            uint32_t bfr[2][4][2];
            #pragma unroll
            for (int mt = 0; mt < 4; mt++) {
                uint32_t ra = base + (arow + mt*16) * ROWB + ks*32 + kcol;
                ldsm4(af[0][mt][0], af[0][mt][1], af[0][mt][2], af[0][mt][3], ra);
                ldsm4(af[1][mt][0], af[1][mt][1], af[1][mt][2], af[1][mt][3], ra + TILEB);
            }
            #pragma unroll
            for (int np = 0; np < 2; np++) {
                // B is K-major [N,K]: NON-trans ldmatrix yields the mma B fragment
                // (lane l gets (n=l/4, k=(l%4)*2+i) == required (k,n) element set).
                uint32_t rb = base + 2*TILEB + (brow + np*16) * ROWB + ks*32 + kcol;
                uint32_t r0, r1, r2, r3;
                ldsm4(r0, r1, r2, r3, rb);
                bfr[0][np*2][0] = r0;   bfr[0][np*2][1]   = r2;   // n-tile lo: b0=k0-7, b1=k8-15
                bfr[0][np*2+1][0] = r1; bfr[0][np*2+1][1] = r3;   // n-tile hi
                ldsm4(r0, r1, r2, r3, rb + TILEB);
                bfr[1][np*2][0] = r0;   bfr[1][np*2][1]   = r2;
                bfr[1][np*2+1][0] = r1; bfr[1][np*2+1][1] = r3;
            }
            #pragma unroll
            for (int mt = 0; mt < 4; mt++)
                #pragma unroll
                for (int nt = 0; nt < 4; nt++) {
                    mma16816(acc[mt][nt], af[0][mt], bfr[0][nt]);  // hi*hi
                    mma16816(acc[mt][nt], af[0][mt], bfr[1][nt]);  // hi*lo
                    mma16816(acc[mt][nt], af[1][mt], bfr[0][nt]);  // lo*hi
                }
        }
        __syncthreads();
        if (pf) { sts(nb); __syncthreads(); }
    }

    // epilogue
    int tg = lane >> 2, t4 = lane & 3;
    #pragma unroll
    for (int mt = 0; mt < 4; mt++)
        #pragma unroll
        for (int rp = 0; rp < 2; rp++) {
            int m = by*128 + wm*64 + mt*16 + tg + rp*8;
            #pragma unroll
            for (int nt = 0; nt < 4; nt++) {
                int col = bx*128 + wn*32 + nt*8 + t4*2;
                float c0 = acc[mt][nt][rp*2+0], c1 = acc[mt][nt][rp*2+1];
                if (OUT == 0) {
                    *(float2*)(Cf + (long long)m * ldc + col) = make_float2(c0, c1);
                } else if (OUT == 1) {
                    bf16 h0,l0,h1,l1;
                    split(c0, h0, l0); split(c1, h1, l1);
                    *(uint32_t*)(Chi + (long long)m * ldc + col) = pack2(h0, h1);
                    *(uint32_t*)(Clo + (long long)m * ldc + col) = pack2(l0, l1);
                } else {
                    bf16 h0,l0,h1,l1;
                    split(c0, h0, l0); split(c1, h1, l1);
                    Chi[(long long)col * ldc + m] = h0;       Clo[(long long)col * ldc + m] = l0;
                    Chi[(long long)(col+1) * ldc + m] = h1;   Clo[(long long)(col+1) * ldc + m] = l1;
                }
            }
        }
}

// ---------------- softmax: fp32 scores -> bf16 hi/lo probs ----------------
__device__ __forceinline__ float blockReduce(float v, bool isMax) {
    __shared__ float sh[8];
    #pragma unroll
    for (int o = 16; o; o >>= 1) {
        float t = __shfl_xor_sync(0xffffffffu, v, o);
        v = isMax ? fmaxf(v, t) : (v + t);
    }
    int w = threadIdx.x >> 5, l = threadIdx.x & 31;
    if (l == 0) sh[w] = v;
    __syncthreads();
    if (w == 0) {
        float t = (l < 8) ? sh[l] : (isMax ? -INFINITY : 0.f);
        #pragma unroll
        for (int o = 4; o; o >>= 1) {
            float u = __shfl_xor_sync(0xffffffffu, t, o);
            t = isMax ? fmaxf(t, u) : (t + u);
        }
        if (l == 0) sh[0] = t;
    }
    __syncthreads();
    float r = sh[0];
    __syncthreads();
    return r;
}

__global__ void softmax_kernel(float* __restrict__ scores, const int* __restrict__ mask,
                               bf16* __restrict__ phi, bf16* __restrict__ plo) {
    int s = blockIdx.x, h = blockIdx.y;
    size_t rbase = ((size_t)h * SEQ + s) * SEQ;
    float* row = scores + rbase;
    int valid = s + 1;
    const float scale = 0.088388347648318447f;   // 1/sqrt(128)
    float mx = -INFINITY;
    for (int t = threadIdx.x; t < valid; t += blockDim.x)
        if (mask[t] != 0) mx = fmaxf(mx, row[t] * scale);
    mx = blockReduce(mx, true);
    float sum = 0.f;
    for (int t = threadIdx.x; t < valid; t += blockDim.x) {
        float e = (mask[t] != 0) ? expf(row[t] * scale - mx) : 0.f;
        row[t] = e;
        sum += e;
    }
    sum = blockReduce(sum, false);
    float invsum = 1.f / sum;
    for (int t = threadIdx.x; t < valid; t += blockDim.x) {
        float p = row[t] * invsum;
        bf16 hh, ll; split(p, hh, ll);
        phi[rbase + t] = hh; plo[rbase + t] = ll;
    }
    int zend = ((s >> 7) + 1) << 7;              // zero-fill through diagonal 128-block
    bf16 z = __float2bfloat16(0.f);
    for (int t = valid + threadIdx.x; t < zend; t += blockDim.x) {
        phi[rbase + t] = z; plo[rbase + t] = z;
    }
}

// ---------------- launch ----------------
extern "C" void kernel_launch(void* const* d_in, const int* in_sizes, int n_in,
                              void* d_out, int out_size) {
    const float* x    = (const float*)d_in[0];
    const int*   mask = (const int*)d_in[1];
    const float* wq   = (const float*)d_in[2];
    const float* wk   = (const float*)d_in[3];
    const float* wv   = (const float*)d_in[4];
    const float* wo   = (const float*)d_in[5];

    bf16 *xhi, *xlo, *whi, *wlo, *qhi, *qlo, *khi, *klo, *vthi, *vtlo, *phi, *plo, *ahi, *alo;
    float *qf, *kf, *sc;
    cudaGetSymbolAddress((void**)&xhi,  g_xhi);  cudaGetSymbolAddress((void**)&xlo,  g_xlo);
    cudaGetSymbolAddress((void**)&whi,  g_whi);  cudaGetSymbolAddress((void**)&wlo,  g_wlo);
    cudaGetSymbolAddress((void**)&qf,   g_qf);   cudaGetSymbolAddress((void**)&kf,   g_kf);
    cudaGetSymbolAddress((void**)&qhi,  g_qhi);  cudaGetSymbolAddress((void**)&qlo,  g_qlo);
    cudaGetSymbolAddress((void**)&khi,  g_khi);  cudaGetSymbolAddress((void**)&klo,  g_klo);
    cudaGetSymbolAddress((void**)&vthi, g_vthi); cudaGetSymbolAddress((void**)&vtlo, g_vtlo);
    cudaGetSymbolAddress((void**)&sc,   g_s);
    cudaGetSymbolAddress((void**)&phi,  g_phi);  cudaGetSymbolAddress((void**)&plo,  g_plo);
    cudaGetSymbolAddress((void**)&ahi,  g_ahi);  cudaGetSymbolAddress((void**)&alo,  g_alo);

    const size_t WSZ = (size_t)HID * HID;

    cudaFuncSetAttribute(gemm_mma<0,false,false>, cudaFuncAttributeMaxDynamicSharedMemorySize, SMEM_SZ);
    cudaFuncSetAttribute(gemm_mma<2,false,false>, cudaFuncAttributeMaxDynamicSharedMemorySize, SMEM_SZ);
    cudaFuncSetAttribute(gemm_mma<0,true, false>, cudaFuncAttributeMaxDynamicSharedMemorySize, SMEM_SZ);
    cudaFuncSetAttribute(gemm_mma<1,false,true >, cudaFuncAttributeMaxDynamicSharedMemorySize, SMEM_SZ);

    // 1. quantize weights -> bf16 hi/lo
    quantize_kernel<<<dim3(GROUPS_PER_W / 8, 4), 256>>>(wq, wk, wv, wo);

    // 2. x -> bf16 hi/lo
    convert_kernel<<<(SEQ * HID / 4) / 256, 256>>>(x, xhi, xlo);

    // 3. projections
    dim3 g16(16, 16, 1);
    gemm_mma<0,false,false><<<g16, 256, SMEM_SZ>>>(xhi, xlo, whi,           wlo,           qf, 0, 0,
                                                   HID, HID, HID, HID, 0, 0, 0);
    gemm_mma<0,false,false><<<g16, 256, SMEM_SZ>>>(xhi, xlo, whi + WSZ,     wlo + WSZ,     kf, 0, 0,
                                                   HID, HID, HID, HID, 0, 0, 0);
    // V projection -> transposed split [o][t]
    gemm_mma<2,false,false><<<g16, 256, SMEM_SZ>>>(xhi, xlo, whi + 2 * WSZ, wlo + 2 * WSZ, 0, vthi, vtlo,
                                                   HID, HID, HID, SEQ, 0, 0, 0);

    // 4. RoPE -> bf16 hi/lo
    rope_kernel<<<dim3(SEQ * NHEADS * 64 / 256, 2), 256>>>(qf, kf, qhi, qlo, khi, klo);

    // 5. scores = Q K^T per head (causal block skip), fp32 out
    gemm_mma<0,true,false><<<dim3(16, 16, NHEADS), 256, SMEM_SZ>>>(
        qhi, qlo, khi, klo, sc, 0, 0,
        HDIM, HID, HID, SEQ, /*sA=*/HDIM, /*sB=*/HDIM, /*sC=*/(long long)SEQ * SEQ);

    // 6. softmax -> P bf16 hi/lo (zero-filled through diagonal block)
    softmax_kernel<<<dim3(SEQ, NHEADS), 256>>>(sc, mask, phi, plo);

    // 7. attn = P V per head (causal K-limit), split out into [s, h*128+d]
    gemm_mma<1,false,true><<<dim3(1, 16, NHEADS), 256, SMEM_SZ>>>(
        phi, plo, vthi, vtlo, 0, ahi, alo,
        SEQ, SEQ, SEQ, HID, /*sA=*/(long long)SEQ * SEQ, /*sB=*/(long long)HDIM * SEQ, /*sC=*/HDIM);

    // 8. out = attn @ Wo^T -> d_out
    gemm_mma<0,false,false><<<g16, 256, SMEM_SZ>>>(ahi, alo, whi + 3 * WSZ, wlo + 3 * WSZ,
                                                   (float*)d_out, 0, 0,
                                                   HID, HID, HID, HID, 0, 0, 0);
}